// round 8
// baseline (speedup 1.0000x reference)
#include <cuda_runtime.h>
#include <cstdint>

#define T_STEPS 512

__device__ uint2 g_keys[T_STEPS];
__device__ __align__(8) float g_w3t[400 * 120];           // conv3 weights [k][o]
__device__ float g_drive1[(size_t)T_STEPS * 32 * 4704];   // conv1 drive [t][b][4704]

// ---------------- threefry2x32 (JAX), 20 rounds ----------------
__device__ __forceinline__ void threefry(unsigned k0, unsigned k1,
                                         unsigned x0, unsigned x1,
                                         unsigned &o0, unsigned &o1)
{
    unsigned k2 = k0 ^ k1 ^ 0x1BD11BDAu;
    x0 += k0; x1 += k1;
#define TF_R(r) { x0 += x1; x1 = __funnelshift_l(x1, x1, (r)); x1 ^= x0; }
    TF_R(13) TF_R(15) TF_R(26) TF_R(6)
    x0 += k1; x1 += k2 + 1u;
    TF_R(17) TF_R(29) TF_R(16) TF_R(24)
    x0 += k2; x1 += k0 + 2u;
    TF_R(13) TF_R(15) TF_R(26) TF_R(6)
    x0 += k0; x1 += k1 + 3u;
    TF_R(17) TF_R(29) TF_R(16) TF_R(24)
    x0 += k1; x1 += k2 + 4u;
    TF_R(13) TF_R(15) TF_R(26) TF_R(6)
    x0 += k2; x1 += k0 + 5u;
#undef TF_R
    o0 = x0; o1 = x1;
}

__global__ void keys_kernel()
{
    int t = threadIdx.x;
    if (t < T_STEPS) {
        unsigned a, b;
        threefry(0u, 1u, 0u, (unsigned)t, a, b);
        g_keys[t] = make_uint2(a, b);
    }
}

__global__ void __launch_bounds__(256) w3t_kernel(const float* __restrict__ w3)
{
    int i = blockIdx.x * 256 + threadIdx.x;   // 48000
    if (i < 48000) {
        int k = i / 120, o = i % 120;
        g_w3t[i] = w3[o * 400 + k];
    }
}

// ---- precompute: spikes (threefry Bernoulli) + conv1, one block per (t,b) ----
__global__ void __launch_bounds__(256) drive1_kernel(const float* __restrict__ image,
                                                     const float* __restrict__ w1)
{
    int blk = blockIdx.x;            // t*32 + b
    int t = blk >> 5, b = blk & 31;
    __shared__ float xf[1024];
    __shared__ float w1s[150];
    int tid = threadIdx.x;
    uint2 k = g_keys[t];
#pragma unroll
    for (int q = 0; q < 4; q++) {
        int i = tid + 256 * q;
        unsigned o0, o1;
        threefry(k.x, k.y, 0u, (unsigned)(b * 1024 + i), o0, o1);
        unsigned bits = o0 ^ o1;
        float u = __uint_as_float(0x3f800000u | (bits >> 9)) - 1.0f;
        float r = __ldg(image + b * 1024 + i) * 0.1953125f;
        xf[i] = (r > u) ? 1.f : 0.f;
    }
    if (tid < 150) w1s[tid] = w1[tid];
    __syncthreads();

    if (tid < 168) {                 // (c, oy): full 28-wide output row
        int c = tid / 28, oy = tid % 28;
        const float* wr = w1s + c * 25;
        float acc[28];
#pragma unroll
        for (int ox = 0; ox < 28; ox++) acc[ox] = 0.f;
#pragma unroll
        for (int ky = 0; ky < 5; ky++) {
            const float* row = xf + (oy + ky) * 32;
            float rv[32];
#pragma unroll
            for (int j = 0; j < 8; j++) {
                float4 v = *(const float4*)(row + 4 * j);
                rv[4*j] = v.x; rv[4*j+1] = v.y; rv[4*j+2] = v.z; rv[4*j+3] = v.w;
            }
#pragma unroll
            for (int kx = 0; kx < 5; kx++) {
                float wv = wr[ky * 5 + kx];
#pragma unroll
                for (int ox = 0; ox < 28; ox++)
                    acc[ox] = fmaf(wv, rv[ox + kx], acc[ox]);
            }
        }
        float* outp = g_drive1 + (size_t)blk * 4704 + tid * 28;
#pragma unroll
        for (int j = 0; j < 7; j++)
            *(float4*)(outp + 4 * j) = make_float4(acc[4*j], acc[4*j+1], acc[4*j+2], acc[4*j+3]);
    }
}

typedef unsigned long long u64;
__device__ __forceinline__ void add2(u64 &acc, u64 p)
{
    asm("add.rn.f32x2 %0, %1, %2;" : "=l"(acc) : "l"(p), "l"(acc));
}
__device__ __forceinline__ float2 u2f(u64 v)
{
    float2 r;
    asm("mov.b64 {%0, %1}, %2;" : "=f"(r.x), "=f"(r.y) : "l"(v));
    return r;
}

// ---------------- shared memory map (float offsets) ----------------
#define SM_DRV    0        // 9408 = 2 x 4704 (double buffer)
#define SM_SKB    9408     // 1176
#define SM_M12A   10584    // 9408
#define SM_M12C   19992    // 3200
#define SM_PARTC  23192    // 360
#define SM_SKE    23552    // 120
#define SM_M12F   23672    // 168
#define SM_SKF    23840    // 84
#define SM_M12G   23924    // 20
#define SM_ACC    23944    // 10
#define SM_WCNT   23954    // 13 ints
#define SM_LIST   23968    // 416 ints
#define SM_W2     24384    // 2400
#define SM_FW1    26784    // 10080
#define SM_FW2    36864    // 840
#define SM_TOTAL  37704
#define SMEM_BYTES (SM_TOTAL * 4)
#define SM_ZBEG   SM_SKB
#define SM_ZEND   SM_W2

__global__ void __launch_bounds__(1024, 1)
sim_kernel(const float* __restrict__ w2, const float* __restrict__ fw1,
           const float* __restrict__ fw2, float* __restrict__ out)
{
    extern __shared__ float sm[];
    int* const wcnt  = (int*)(sm + SM_WCNT);
    int* const listi = (int*)(sm + SM_LIST);

    const int tid  = threadIdx.x;
    const int b    = blockIdx.x;
    const int lane = tid & 31;
    const int wrp  = tid >> 5;

    for (int i = tid; i < 2400;  i += 1024) sm[SM_W2  + i] = w2[i];
    for (int i = tid; i < 10080; i += 1024) sm[SM_FW1 + i] = fw1[i];
    for (int i = tid; i < 840;   i += 1024) sm[SM_FW2 + i] = fw2[i];
    for (int i = tid; i < (SM_ZEND - SM_ZBEG); i += 1024) sm[SM_ZBEG + i] = 0.0f;
    {   // preload drive for t=0
        const float4* src = (const float4*)(g_drive1 + (size_t)b * 4704);
        float4* dst = (float4*)(sm + SM_DRV);
        for (int i = tid; i < 1176; i += 1024) dst[i] = src[i];
    }
    __syncthreads();

    // ---- static mappings ----
    const int a_c  = tid / 98;                 // A: tid<588 (c, by, p)
    const int a_r  = tid % 98;
    const int a_by = a_r / 7;
    const int a_p  = a_r % 7;
    const int b_oc = tid / 25;                 // B: tid<400 (oc, py, px)
    const int b_rm = tid % 25;
    const int b_py = b_rm / 5;
    const int b_px = b_rm % 5;
    const int c_sp = tid >> 7;                 // C1: tid<512, o2<60
    const int c_o2 = tid & 127;
    const int d_g  = tid >> 3;                 // D: tid<672
    const int d_j  = tid & 7;

    // register-resident LIF state
    float pm1[2] = {0.f, 0.f}, pm2[2] = {0.f, 0.f};       // layer2 pooled
    float qm1 = 0.f, qm2 = 0.f;                            // layer4 pooled
    float em1a = 0.f, em2a = 0.f, em1b = 0.f, em2b = 0.f;  // layer5

#pragma unroll 1
    for (int t = 0; t < T_STEPS; t++) {
        // ---- A': lif1(drive from smem) + pool + lif2 -> SKB ----
        if (tid < 588) {
            const float* dp = sm + SM_DRV + (t & 1) * 4704
                            + a_c * 784 + (2 * a_by) * 28 + 4 * a_p;
            float4 v0 = *(const float4*)dp;
            float4 v1 = *(const float4*)(dp + 28);
            float acc[8] = {v0.x, v0.y, v0.z, v0.w, v1.x, v1.y, v1.z, v1.w};
            int ob = a_c * 784 + (2 * a_by) * 28 + 4 * a_p;
            float ps[2] = {0.f, 0.f};
#pragma unroll
            for (int q = 0; q < 8; q++) {
                int oy = q >> 2, j = q & 3;
                int o = ob + oy * 28 + j;
                float2 m = *(float2*)(sm + SM_M12A + 2 * o);
                float oms = (m.y > 0.3f) ? 0.f : 1.f;
                float n1 = m.x * 0.25f * oms + acc[q];
                float n2 = m.y * 0.25f * oms + 0.5f * n1;
                *(float2*)(sm + SM_M12A + 2 * o) = make_float2(n1, n2);
                ps[j >> 1] += (n2 > 0.3f) ? 1.f : 0.f;
            }
#pragma unroll
            for (int h = 0; h < 2; h++) {
                float d   = 0.25f * ps[h];
                float oms = (pm2[h] > 0.3f) ? 0.f : 1.f;
                float n1  = pm1[h] * 0.25f * oms + d;
                float n2  = pm2[h] * 0.25f * oms + 0.5f * n1;
                pm1[h] = n1; pm2[h] = n2;
                sm[SM_SKB + a_c * 196 + a_by * 14 + 2 * a_p + h] = (n2 > 0.3f) ? 1.f : 0.f;
            }
        }
        __syncthreads();

        // ---- B: conv2 fused (all ic) + lif3 + pool + lif4 | drive prefetch ----
        bool spiked = false;
        int myk = 0;
        if (tid < 400) {
            float a00 = 0.f, a01 = 0.f, a10 = 0.f, a11 = 0.f;
            const float* wb = sm + SM_W2 + b_oc * 150;
#pragma unroll
            for (int ic = 0; ic < 6; ic++) {
                const float* ib = sm + SM_SKB + ic * 196 + (2 * b_py) * 14 + 2 * b_px;
                const float* wr = wb + ic * 25;
                float in[6][6];
#pragma unroll
                for (int r = 0; r < 6; r++) {
                    const float* rp = ib + r * 14;
                    float2 x0 = *(const float2*)rp;
                    float2 x1 = *(const float2*)(rp + 2);
                    float2 x2 = *(const float2*)(rp + 4);
                    in[r][0] = x0.x; in[r][1] = x0.y; in[r][2] = x1.x;
                    in[r][3] = x1.y; in[r][4] = x2.x; in[r][5] = x2.y;
                }
#pragma unroll
                for (int ky = 0; ky < 5; ky++)
#pragma unroll
                    for (int kx = 0; kx < 5; kx++) {
                        float wv = wr[ky * 5 + kx];
                        a00 = fmaf(wv, in[ky][kx],         a00);
                        a01 = fmaf(wv, in[ky][kx + 1],     a01);
                        a10 = fmaf(wv, in[ky + 1][kx],     a10);
                        a11 = fmaf(wv, in[ky + 1][kx + 1], a11);
                    }
            }
            float dr0[4] = {a00, a01, a10, a11};
            float psum = 0.f;
            int ob = b_oc * 100 + (2 * b_py) * 10 + 2 * b_px;
#pragma unroll
            for (int q = 0; q < 4; q++) {
                int o = ob + (q >> 1) * 10 + (q & 1);
                float2 m = *(float2*)(sm + SM_M12C + 2 * o);
                float oms = (m.y > 0.3f) ? 0.f : 1.f;
                float n1 = m.x * 0.25f * oms + dr0[q];
                float n2 = m.y * 0.25f * oms + 0.5f * n1;
                *(float2*)(sm + SM_M12C + 2 * o) = make_float2(n1, n2);
                psum += (n2 > 0.3f) ? 1.f : 0.f;
            }
            float d   = 0.25f * psum;
            float oms = (qm2 > 0.3f) ? 0.f : 1.f;
            float n1  = qm1 * 0.25f * oms + d;
            float n2  = qm2 * 0.25f * oms + 0.5f * n1;
            qm1 = n1; qm2 = n2;
            if (n2 > 0.3f) { spiked = true; myk = tid; }
        }
        if (wrp < 13) {
            unsigned bm = __ballot_sync(0xffffffffu, spiked);
            if (spiked) listi[wrp * 32 + __popc(bm & ((1u << lane) - 1u))] = myk;
            if (lane == 0) wcnt[wrp] = __popc(bm);
        } else if (wrp >= 16 && t + 1 < T_STEPS) {
            const float4* src = (const float4*)(g_drive1 + ((size_t)(t + 1) * 32 + b) * 4704);
            float4* dst = (float4*)(sm + SM_DRV + ((t + 1) & 1) * 4704);
            for (int i = tid - 512; i < 1176; i += 512) dst[i] = src[i];
        }
        __syncthreads();

        // ---- C1: sparse conv3 gather (u64 pairs), 4-way segment split ----
        u64 cacc = 0ull;
        if (tid < 512 && c_o2 < 60) {
            const u64* w3p = (const u64*)g_w3t;
            for (int w = c_sp; w < 13; w += 4) {
                int n = wcnt[w];
                const int* seg = listi + w * 32;
                for (int j = 0; j < n; j++) {
                    int k = seg[j];
                    add2(cacc, __ldg(w3p + k * 60 + c_o2));
                }
            }
            if (c_sp) *(u64*)(sm + SM_PARTC + (c_sp - 1) * 120 + 2 * c_o2) = cacc;
        }
        __syncthreads();

        // ---- C2: combine + lif5 -> SKE ----
        if (tid < 60) {
            add2(cacc, *(const u64*)(sm + SM_PARTC + 2 * tid));
            add2(cacc, *(const u64*)(sm + SM_PARTC + 120 + 2 * tid));
            add2(cacc, *(const u64*)(sm + SM_PARTC + 240 + 2 * tid));
            float2 v = u2f(cacc);
            float oms = (em2a > 0.3f) ? 0.f : 1.f;
            float n1  = em1a * 0.25f * oms + v.x;
            float n2  = em2a * 0.25f * oms + 0.5f * n1;
            em1a = n1; em2a = n2;
            sm[SM_SKE + 2 * tid] = (n2 > 0.3f) ? 1.f : 0.f;
            float omsb = (em2b > 0.3f) ? 0.f : 1.f;
            float n1b  = em1b * 0.25f * omsb + v.y;
            float n2b  = em2b * 0.25f * omsb + 0.5f * n1b;
            em1b = n1b; em2b = n2b;
            sm[SM_SKE + 2 * tid + 1] = (n2b > 0.3f) ? 1.f : 0.f;
        }
        __syncthreads();

        // ---- D: fc1 + lif6 -> SKF ----
        if (tid < 672) {
            const float* wp = sm + SM_FW1 + d_g * 120;
            float s = 0.f;
#pragma unroll
            for (int k = d_j; k < 120; k += 8) s = fmaf(wp[k], sm[SM_SKE + k], s);
            s += __shfl_xor_sync(0xffffffffu, s, 4);
            s += __shfl_xor_sync(0xffffffffu, s, 2);
            s += __shfl_xor_sync(0xffffffffu, s, 1);
            if (d_j == 0) {
                float2 m = *(float2*)(sm + SM_M12F + 2 * d_g);
                float oms = (m.y > 0.3f) ? 0.f : 1.f;
                float n1 = m.x * 0.25f * oms + s;
                float n2 = m.y * 0.25f * oms + 0.5f * n1;
                *(float2*)(sm + SM_M12F + 2 * d_g) = make_float2(n1, n2);
                sm[SM_SKF + d_g] = (n2 > 0.3f) ? 1.f : 0.f;
            }
        }
        __syncthreads();

        // ---- E: fc2 + lif7 + acc (warps 0-9) ----
        if (wrp < 10) {
            const float* wp = sm + SM_FW2 + wrp * 84;
            float s = 0.f;
            for (int k = lane; k < 84; k += 32) s = fmaf(wp[k], sm[SM_SKF + k], s);
#pragma unroll
            for (int d2 = 16; d2 > 0; d2 >>= 1) s += __shfl_xor_sync(0xffffffffu, s, d2);
            if (lane == 0) {
                float2 m = *(float2*)(sm + SM_M12G + 2 * wrp);
                float oms = (m.y > 0.3f) ? 0.f : 1.f;
                float n1 = m.x * 0.25f * oms + s;
                float n2 = m.y * 0.25f * oms + 0.5f * n1;
                *(float2*)(sm + SM_M12G + 2 * wrp) = make_float2(n1, n2);
                sm[SM_ACC + wrp] += (n2 > 0.3f) ? 1.f : 0.f;
            }
        }
        __syncthreads();
    }

    if (tid < 10)
        out[b * 10 + tid] = sm[SM_ACC + tid] * (1.0f / 512.0f);
}

extern "C" void kernel_launch(void* const* d_in, const int* in_sizes, int n_in,
                              void* d_out, int out_size)
{
    const float* image = (const float*)d_in[0];
    const float* w1    = (const float*)d_in[1];
    const float* w2    = (const float*)d_in[2];
    const float* w3    = (const float*)d_in[3];
    const float* fw1   = (const float*)d_in[4];
    const float* fw2   = (const float*)d_in[5];
    float* out = (float*)d_out;

    keys_kernel<<<1, 512>>>();
    drive1_kernel<<<T_STEPS * 32, 256>>>(image, w1);
    w3t_kernel<<<(48000 + 255) / 256, 256>>>(w3);
    cudaFuncSetAttribute(sim_kernel, cudaFuncAttributeMaxDynamicSharedMemorySize, SMEM_BYTES);
    sim_kernel<<<32, 1024, SMEM_BYTES>>>(w2, fw1, fw2, out);
}

// round 9
// speedup vs baseline: 1.1589x; 1.1589x over previous
#include <cuda_runtime.h>
#include <cstdint>

#define T_STEPS 512
#define N_SIM   32
#define N_PROD  116
#define N_TILES (T_STEPS * 32)

__device__ __align__(8) float g_w3t[400 * 120];           // conv3 weights [k][o]
__device__ float g_drive1[(size_t)N_TILES * 4704];        // conv1 drive [t][b][4704]
__device__ int   g_ready[N_TILES];

// ---------------- threefry2x32 (JAX), 20 rounds ----------------
__device__ __forceinline__ void threefry(unsigned k0, unsigned k1,
                                         unsigned x0, unsigned x1,
                                         unsigned &o0, unsigned &o1)
{
    unsigned k2 = k0 ^ k1 ^ 0x1BD11BDAu;
    x0 += k0; x1 += k1;
#define TF_R(r) { x0 += x1; x1 = __funnelshift_l(x1, x1, (r)); x1 ^= x0; }
    TF_R(13) TF_R(15) TF_R(26) TF_R(6)
    x0 += k1; x1 += k2 + 1u;
    TF_R(17) TF_R(29) TF_R(16) TF_R(24)
    x0 += k2; x1 += k0 + 2u;
    TF_R(13) TF_R(15) TF_R(26) TF_R(6)
    x0 += k0; x1 += k1 + 3u;
    TF_R(17) TF_R(29) TF_R(16) TF_R(24)
    x0 += k1; x1 += k2 + 4u;
    TF_R(13) TF_R(15) TF_R(26) TF_R(6)
    x0 += k2; x1 += k0 + 5u;
#undef TF_R
    o0 = x0; o1 = x1;
}

__global__ void __launch_bounds__(1024) reset_kernel()
{
    int i = blockIdx.x * 1024 + threadIdx.x;
    if (i < N_TILES) g_ready[i] = 0;
}

__global__ void __launch_bounds__(256) w3t_kernel(const float* __restrict__ w3)
{
    int i = blockIdx.x * 256 + threadIdx.x;   // 48000
    if (i < 48000) {
        int k = i / 120, o = i % 120;
        g_w3t[i] = w3[o * 400 + k];
    }
}

typedef unsigned long long u64;
__device__ __forceinline__ void add2(u64 &acc, u64 p)
{
    asm("add.rn.f32x2 %0, %1, %2;" : "=l"(acc) : "l"(p), "l"(acc));
}
__device__ __forceinline__ float2 u2f(u64 v)
{
    float2 r;
    asm("mov.b64 {%0, %1}, %2;" : "=f"(r.x), "=f"(r.y) : "l"(v));
    return r;
}

// ---------------- shared memory map (float offsets) ----------------
#define SM_DRV    0        // 9408 = 2 x 4704 (double buffer)
#define SM_SKB    9408     // 1176
#define SM_M12A   10584    // 9408
#define SM_M12C   19992    // 3200
#define SM_PARTC  23192    // 360
#define SM_SKE    23552    // 120
#define SM_M12F   23672    // 168
#define SM_SKF    23840    // 84
#define SM_M12G   23924    // 20
#define SM_ACC    23944    // 10
#define SM_WCNT   23954    // 13 ints
#define SM_LIST   23968    // 416 ints
#define SM_W2     24384    // 2400
#define SM_FW1    26784    // 10080
#define SM_FW2    36864    // 840
#define SM_TOTAL  37704
#define SMEM_BYTES (SM_TOTAL * 4)
#define SM_ZBEG   SM_SKB
#define SM_ZEND   SM_W2
// producer view of the same smem
#define PM_XF     0        // 1024
#define PM_W1     1024     // 150

__global__ void __launch_bounds__(1024, 1)
fused_kernel(const float* __restrict__ image, const float* __restrict__ w1,
             const float* __restrict__ w2, const float* __restrict__ fw1,
             const float* __restrict__ fw2, float* __restrict__ out)
{
    extern __shared__ float sm[];
    const int tid  = threadIdx.x;
    const int lane = tid & 31;
    const int wrp  = tid >> 5;

    if (blockIdx.x >= N_SIM) {
        // ================= PRODUCER: RNG + conv1 for tiles (t,b) =================
        const int p = blockIdx.x - N_SIM;
        if (tid < 150) sm[PM_W1 + tid] = w1[tid];
        __syncthreads();
        const int c1_c  = tid / 112;           // conv1: tid<672
        const int c1_r  = tid % 112;
        const int c1_oy = c1_r >> 2;
        const int c1_x0 = (c1_r & 3) * 7;

        for (int idx = p; idx < N_TILES; idx += N_PROD) {
            int t = idx >> 5, b = idx & 31;
            unsigned k0, k1;
            threefry(0u, 1u, 0u, (unsigned)t, k0, k1);   // per-step key
            unsigned o0, o1;
            threefry(k0, k1, 0u, (unsigned)(b * 1024 + tid), o0, o1);
            unsigned bits = o0 ^ o1;
            float u = __uint_as_float(0x3f800000u | (bits >> 9)) - 1.0f;
            float r = __ldg(image + b * 1024 + tid) * 0.1953125f;
            sm[PM_XF + tid] = (r > u) ? 1.f : 0.f;
            __syncthreads();

            if (tid < 672) {
                const float* wr = sm + PM_W1 + c1_c * 25;
                float acc[7];
#pragma unroll
                for (int o = 0; o < 7; o++) acc[o] = 0.f;
#pragma unroll
                for (int ky = 0; ky < 5; ky++) {
                    const float* row = sm + PM_XF + (c1_oy + ky) * 32 + c1_x0;
                    float in[11];
#pragma unroll
                    for (int q = 0; q < 11; q++) in[q] = row[q];
#pragma unroll
                    for (int kx = 0; kx < 5; kx++) {
                        float wv = wr[ky * 5 + kx];
#pragma unroll
                        for (int o = 0; o < 7; o++)
                            acc[o] = fmaf(wv, in[kx + o], acc[o]);
                    }
                }
                float* outp = g_drive1 + (size_t)idx * 4704
                            + c1_c * 784 + c1_oy * 28 + c1_x0;
#pragma unroll
                for (int o = 0; o < 7; o++) outp[o] = acc[o];
            }
            __syncthreads();
            if (tid == 0) {
                __threadfence();
                ((volatile int*)g_ready)[idx] = 1;
            }
        }
        return;
    }

    // ================= SIM CTA (one per batch element) =================
    int* const wcnt  = (int*)(sm + SM_WCNT);
    int* const listi = (int*)(sm + SM_LIST);
    const int b = blockIdx.x;

    for (int i = tid; i < 2400;  i += 1024) sm[SM_W2  + i] = w2[i];
    for (int i = tid; i < 10080; i += 1024) sm[SM_FW1 + i] = fw1[i];
    for (int i = tid; i < 840;   i += 1024) sm[SM_FW2 + i] = fw2[i];
    for (int i = tid; i < (SM_ZEND - SM_ZBEG); i += 1024) sm[SM_ZBEG + i] = 0.0f;
    // wait for tile (0,b) and preload into buffer 0
    if (tid == 0) {
        while (((volatile int*)g_ready)[b] == 0) __nanosleep(64);
    }
    __syncthreads();
    __threadfence();
    {
        const float4* src = (const float4*)(g_drive1 + (size_t)b * 4704);
        float4* dst = (float4*)(sm + SM_DRV);
        for (int i = tid; i < 1176; i += 1024) dst[i] = src[i];
    }
    __syncthreads();

    // ---- static mappings ----
    const int a_c  = tid / 98;                 // A: tid<588 (c, by, p)
    const int a_r  = tid % 98;
    const int a_by = a_r / 7;
    const int a_p  = a_r % 7;
    const int b_oc = tid / 25;                 // B: tid<400 (oc, py, px)
    const int b_rm = tid % 25;
    const int b_py = b_rm / 5;
    const int b_px = b_rm % 5;
    const int c_sp = tid >> 7;                 // C1: tid<512, o2<60
    const int c_o2 = tid & 127;
    const int d_g  = tid >> 3;                 // D: tid<672
    const int d_j  = tid & 7;

    // register-resident LIF state
    float pm1[2] = {0.f, 0.f}, pm2[2] = {0.f, 0.f};       // layer2 pooled
    float qm1 = 0.f, qm2 = 0.f;                            // layer4 pooled
    float em1a = 0.f, em2a = 0.f, em1b = 0.f, em2b = 0.f;  // layer5

#pragma unroll 1
    for (int t = 0; t < T_STEPS; t++) {
        // ---- A': lif1(drive from smem) + pool + lif2 -> SKB ----
        if (tid < 588) {
            const float* dp = sm + SM_DRV + (t & 1) * 4704
                            + a_c * 784 + (2 * a_by) * 28 + 4 * a_p;
            float4 v0 = *(const float4*)dp;
            float4 v1 = *(const float4*)(dp + 28);
            float acc[8] = {v0.x, v0.y, v0.z, v0.w, v1.x, v1.y, v1.z, v1.w};
            int ob = a_c * 784 + (2 * a_by) * 28 + 4 * a_p;
            float ps[2] = {0.f, 0.f};
#pragma unroll
            for (int q = 0; q < 8; q++) {
                int oy = q >> 2, j = q & 3;
                int o = ob + oy * 28 + j;
                float2 m = *(float2*)(sm + SM_M12A + 2 * o);
                float oms = (m.y > 0.3f) ? 0.f : 1.f;
                float n1 = m.x * 0.25f * oms + acc[q];
                float n2 = m.y * 0.25f * oms + 0.5f * n1;
                *(float2*)(sm + SM_M12A + 2 * o) = make_float2(n1, n2);
                ps[j >> 1] += (n2 > 0.3f) ? 1.f : 0.f;
            }
#pragma unroll
            for (int h = 0; h < 2; h++) {
                float d   = 0.25f * ps[h];
                float oms = (pm2[h] > 0.3f) ? 0.f : 1.f;
                float n1  = pm1[h] * 0.25f * oms + d;
                float n2  = pm2[h] * 0.25f * oms + 0.5f * n1;
                pm1[h] = n1; pm2[h] = n2;
                sm[SM_SKB + a_c * 196 + a_by * 14 + 2 * a_p + h] = (n2 > 0.3f) ? 1.f : 0.f;
            }
        }
        __syncthreads();

        // ---- B: conv2 fused + lif3 + pool + lif4 | drive(t+1) prefetch ----
        bool spiked = false;
        int myk = 0;
        if (tid < 400) {
            float a00 = 0.f, a01 = 0.f, a10 = 0.f, a11 = 0.f;
            const float* wb = sm + SM_W2 + b_oc * 150;
#pragma unroll
            for (int ic = 0; ic < 6; ic++) {
                const float* ib = sm + SM_SKB + ic * 196 + (2 * b_py) * 14 + 2 * b_px;
                const float* wr = wb + ic * 25;
                float in[6][6];
#pragma unroll
                for (int r = 0; r < 6; r++) {
                    const float* rp = ib + r * 14;
                    float2 x0 = *(const float2*)rp;
                    float2 x1 = *(const float2*)(rp + 2);
                    float2 x2 = *(const float2*)(rp + 4);
                    in[r][0] = x0.x; in[r][1] = x0.y; in[r][2] = x1.x;
                    in[r][3] = x1.y; in[r][4] = x2.x; in[r][5] = x2.y;
                }
#pragma unroll
                for (int ky = 0; ky < 5; ky++)
#pragma unroll
                    for (int kx = 0; kx < 5; kx++) {
                        float wv = wr[ky * 5 + kx];
                        a00 = fmaf(wv, in[ky][kx],         a00);
                        a01 = fmaf(wv, in[ky][kx + 1],     a01);
                        a10 = fmaf(wv, in[ky + 1][kx],     a10);
                        a11 = fmaf(wv, in[ky + 1][kx + 1], a11);
                    }
            }
            float dr0[4] = {a00, a01, a10, a11};
            float psum = 0.f;
            int ob = b_oc * 100 + (2 * b_py) * 10 + 2 * b_px;
#pragma unroll
            for (int q = 0; q < 4; q++) {
                int o = ob + (q >> 1) * 10 + (q & 1);
                float2 m = *(float2*)(sm + SM_M12C + 2 * o);
                float oms = (m.y > 0.3f) ? 0.f : 1.f;
                float n1 = m.x * 0.25f * oms + dr0[q];
                float n2 = m.y * 0.25f * oms + 0.5f * n1;
                *(float2*)(sm + SM_M12C + 2 * o) = make_float2(n1, n2);
                psum += (n2 > 0.3f) ? 1.f : 0.f;
            }
            float d   = 0.25f * psum;
            float oms = (qm2 > 0.3f) ? 0.f : 1.f;
            float n1  = qm1 * 0.25f * oms + d;
            float n2  = qm2 * 0.25f * oms + 0.5f * n1;
            qm1 = n1; qm2 = n2;
            if (n2 > 0.3f) { spiked = true; myk = tid; }
        }
        if (wrp < 13) {
            unsigned bm = __ballot_sync(0xffffffffu, spiked);
            if (spiked) listi[wrp * 32 + __popc(bm & ((1u << lane) - 1u))] = myk;
            if (lane == 0) wcnt[wrp] = __popc(bm);
        } else if (wrp >= 16 && t + 1 < T_STEPS) {
            int idx = (t + 1) * 32 + b;
            if (lane == 0) {
                while (((volatile int*)g_ready)[idx] == 0) __nanosleep(64);
            }
            __syncwarp();
            __threadfence();
            const float4* src = (const float4*)(g_drive1 + (size_t)idx * 4704);
            float4* dst = (float4*)(sm + SM_DRV + ((t + 1) & 1) * 4704);
            for (int i = tid - 512; i < 1176; i += 512) dst[i] = src[i];
        }
        __syncthreads();

        // ---- C1: sparse conv3 gather (u64 pairs), 4-way segment split ----
        u64 cacc = 0ull;
        if (tid < 512 && c_o2 < 60) {
            const u64* w3p = (const u64*)g_w3t;
            for (int w = c_sp; w < 13; w += 4) {
                int n = wcnt[w];
                const int* seg = listi + w * 32;
                for (int j = 0; j < n; j++) {
                    int k = seg[j];
                    add2(cacc, __ldg(w3p + k * 60 + c_o2));
                }
            }
            if (c_sp) *(u64*)(sm + SM_PARTC + (c_sp - 1) * 120 + 2 * c_o2) = cacc;
        }
        __syncthreads();

        // ---- C2: combine + lif5 -> SKE ----
        if (tid < 60) {
            add2(cacc, *(const u64*)(sm + SM_PARTC + 2 * tid));
            add2(cacc, *(const u64*)(sm + SM_PARTC + 120 + 2 * tid));
            add2(cacc, *(const u64*)(sm + SM_PARTC + 240 + 2 * tid));
            float2 v = u2f(cacc);
            float oms = (em2a > 0.3f) ? 0.f : 1.f;
            float n1  = em1a * 0.25f * oms + v.x;
            float n2  = em2a * 0.25f * oms + 0.5f * n1;
            em1a = n1; em2a = n2;
            sm[SM_SKE + 2 * tid] = (n2 > 0.3f) ? 1.f : 0.f;
            float omsb = (em2b > 0.3f) ? 0.f : 1.f;
            float n1b  = em1b * 0.25f * omsb + v.y;
            float n2b  = em2b * 0.25f * omsb + 0.5f * n1b;
            em1b = n1b; em2b = n2b;
            sm[SM_SKE + 2 * tid + 1] = (n2b > 0.3f) ? 1.f : 0.f;
        }
        __syncthreads();

        // ---- D: fc1 + lif6 -> SKF ----
        if (tid < 672) {
            const float* wp = sm + SM_FW1 + d_g * 120;
            float s = 0.f;
#pragma unroll
            for (int k = d_j; k < 120; k += 8) s = fmaf(wp[k], sm[SM_SKE + k], s);
            s += __shfl_xor_sync(0xffffffffu, s, 4);
            s += __shfl_xor_sync(0xffffffffu, s, 2);
            s += __shfl_xor_sync(0xffffffffu, s, 1);
            if (d_j == 0) {
                float2 m = *(float2*)(sm + SM_M12F + 2 * d_g);
                float oms = (m.y > 0.3f) ? 0.f : 1.f;
                float n1 = m.x * 0.25f * oms + s;
                float n2 = m.y * 0.25f * oms + 0.5f * n1;
                *(float2*)(sm + SM_M12F + 2 * d_g) = make_float2(n1, n2);
                sm[SM_SKF + d_g] = (n2 > 0.3f) ? 1.f : 0.f;
            }
        }
        __syncthreads();

        // ---- E: fc2 + lif7 + acc (warps 0-9) ----
        if (wrp < 10) {
            const float* wp = sm + SM_FW2 + wrp * 84;
            float s = 0.f;
            for (int k = lane; k < 84; k += 32) s = fmaf(wp[k], sm[SM_SKF + k], s);
#pragma unroll
            for (int d2 = 16; d2 > 0; d2 >>= 1) s += __shfl_xor_sync(0xffffffffu, s, d2);
            if (lane == 0) {
                float2 m = *(float2*)(sm + SM_M12G + 2 * wrp);
                float oms = (m.y > 0.3f) ? 0.f : 1.f;
                float n1 = m.x * 0.25f * oms + s;
                float n2 = m.y * 0.25f * oms + 0.5f * n1;
                *(float2*)(sm + SM_M12G + 2 * wrp) = make_float2(n1, n2);
                sm[SM_ACC + wrp] += (n2 > 0.3f) ? 1.f : 0.f;
            }
        }
        __syncthreads();
    }

    if (tid < 10)
        out[b * 10 + tid] = sm[SM_ACC + tid] * (1.0f / 512.0f);
}

extern "C" void kernel_launch(void* const* d_in, const int* in_sizes, int n_in,
                              void* d_out, int out_size)
{
    const float* image = (const float*)d_in[0];
    const float* w1    = (const float*)d_in[1];
    const float* w2    = (const float*)d_in[2];
    const float* w3    = (const float*)d_in[3];
    const float* fw1   = (const float*)d_in[4];
    const float* fw2   = (const float*)d_in[5];
    float* out = (float*)d_out;

    reset_kernel<<<(N_TILES + 1023) / 1024, 1024>>>();
    w3t_kernel<<<(48000 + 255) / 256, 256>>>(w3);
    cudaFuncSetAttribute(fused_kernel, cudaFuncAttributeMaxDynamicSharedMemorySize, SMEM_BYTES);
    fused_kernel<<<N_SIM + N_PROD, 1024, SMEM_BYTES>>>(image, w1, w2, fw1, fw2, out);
}

// round 10
// speedup vs baseline: 1.3997x; 1.2077x over previous
#include <cuda_runtime.h>
#include <cstdint>

#define T_STEPS 512
#define N_SIM   32
#define N_PROD  116
#define N_TILES (T_STEPS * 32)

__device__ __align__(8) float g_w3t[400 * 120];       // conv3 weights [k][o]
__device__ float g_drive1[(size_t)N_TILES * 4704];    // conv1 drive [t][b][4704]
__device__ int   g_ready[N_TILES];

// ---------------- threefry2x32 (JAX), 20 rounds ----------------
__device__ __forceinline__ void threefry(unsigned k0, unsigned k1,
                                         unsigned x0, unsigned x1,
                                         unsigned &o0, unsigned &o1)
{
    unsigned k2 = k0 ^ k1 ^ 0x1BD11BDAu;
    x0 += k0; x1 += k1;
#define TF_R(r) { x0 += x1; x1 = __funnelshift_l(x1, x1, (r)); x1 ^= x0; }
    TF_R(13) TF_R(15) TF_R(26) TF_R(6)
    x0 += k1; x1 += k2 + 1u;
    TF_R(17) TF_R(29) TF_R(16) TF_R(24)
    x0 += k2; x1 += k0 + 2u;
    TF_R(13) TF_R(15) TF_R(26) TF_R(6)
    x0 += k0; x1 += k1 + 3u;
    TF_R(17) TF_R(29) TF_R(16) TF_R(24)
    x0 += k1; x1 += k2 + 4u;
    TF_R(13) TF_R(15) TF_R(26) TF_R(6)
    x0 += k2; x1 += k0 + 5u;
#undef TF_R
    o0 = x0; o1 = x1;
}

__global__ void __launch_bounds__(1024) reset_kernel()
{
    int i = blockIdx.x * 1024 + threadIdx.x;
    if (i < N_TILES) g_ready[i] = 0;
}

__global__ void __launch_bounds__(256) w3t_kernel(const float* __restrict__ w3)
{
    int i = blockIdx.x * 256 + threadIdx.x;   // 48000
    if (i < 48000) {
        int k = i / 120, o = i % 120;
        g_w3t[i] = w3[o * 400 + k];
    }
}

typedef unsigned long long u64;
__device__ __forceinline__ void add2(u64 &acc, u64 p)
{
    asm("add.rn.f32x2 %0, %1, %2;" : "=l"(acc) : "l"(p), "l"(acc));
}
__device__ __forceinline__ float2 u2f(u64 v)
{
    float2 r;
    asm("mov.b64 {%0, %1}, %2;" : "=f"(r.x), "=f"(r.y) : "l"(v));
    return r;
}

// ---------------- shared memory map (float offsets) ----------------
#define SM_DRV    0        // 9408 = 2 x 4704 drive double buffer
#define SM_SKB    9408     // 1176
#define SM_M12A   10584    // 9408
#define SM_M12C   19992    // 3200
#define SM_PARTB  23192    // 9600 = ic(6) x oc(16) x 10 x 10
#define SM_PARTC  32792    // 360
#define SM_SKE    33152    // 120
#define SM_M12F   33272    // 168
#define SM_SKF    33440    // 84
#define SM_M12G   33524    // 20
#define SM_ACC    33544    // 10
#define SM_WCNT   33554    // 13 ints
#define SM_LIST   33568    // 416 ints
#define SM_W2     33984    // 2400
#define SM_FW1    36384    // 10080
#define SM_FW2    46464    // 840
#define SM_TOTAL  47304
#define SMEM_BYTES (SM_TOTAL * 4)
#define SM_ZBEG   SM_SKB
#define SM_ZEND   SM_W2
// producer view of the same smem
#define PM_XF     0
#define PM_W1     1024

__global__ void __launch_bounds__(1024, 1)
fused_kernel(const float* __restrict__ image, const float* __restrict__ w1,
             const float* __restrict__ w2, const float* __restrict__ fw1,
             const float* __restrict__ fw2, float* __restrict__ out)
{
    extern __shared__ float sm[];
    const int tid  = threadIdx.x;
    const int lane = tid & 31;
    const int wrp  = tid >> 5;

    if (blockIdx.x >= N_SIM) {
        // ================= PRODUCER: RNG + conv1 for tiles (t,b) =================
        const int p = blockIdx.x - N_SIM;
        if (tid < 150) sm[PM_W1 + tid] = w1[tid];
        __syncthreads();
        const int c1_c  = tid / 112;           // conv1: tid<672
        const int c1_r  = tid % 112;
        const int c1_oy = c1_r >> 2;
        const int c1_x0 = (c1_r & 3) * 7;

        for (int idx = p; idx < N_TILES; idx += N_PROD) {
            int t = idx >> 5, b = idx & 31;
            unsigned k0, k1;
            threefry(0u, 1u, 0u, (unsigned)t, k0, k1);
            unsigned o0, o1;
            threefry(k0, k1, 0u, (unsigned)(b * 1024 + tid), o0, o1);
            unsigned bits = o0 ^ o1;
            float u = __uint_as_float(0x3f800000u | (bits >> 9)) - 1.0f;
            float r = __ldg(image + b * 1024 + tid) * 0.1953125f;
            sm[PM_XF + tid] = (r > u) ? 1.f : 0.f;
            __syncthreads();

            if (tid < 672) {
                const float* wr = sm + PM_W1 + c1_c * 25;
                float acc[7];
#pragma unroll
                for (int o = 0; o < 7; o++) acc[o] = 0.f;
#pragma unroll
                for (int ky = 0; ky < 5; ky++) {
                    const float* row = sm + PM_XF + (c1_oy + ky) * 32 + c1_x0;
                    float in[11];
#pragma unroll
                    for (int q = 0; q < 11; q++) in[q] = row[q];
#pragma unroll
                    for (int kx = 0; kx < 5; kx++) {
                        float wv = wr[ky * 5 + kx];
#pragma unroll
                        for (int o = 0; o < 7; o++)
                            acc[o] = fmaf(wv, in[kx + o], acc[o]);
                    }
                }
                float* outp = g_drive1 + (size_t)idx * 4704
                            + c1_c * 784 + c1_oy * 28 + c1_x0;
#pragma unroll
                for (int o = 0; o < 7; o++) outp[o] = acc[o];
            }
            __syncthreads();
            if (tid == 0) {
                __threadfence();
                ((volatile int*)g_ready)[idx] = 1;
            }
        }
        return;
    }

    // ================= SIM CTA (one per batch element) =================
    int* const wcnt  = (int*)(sm + SM_WCNT);
    int* const listi = (int*)(sm + SM_LIST);
    const int b = blockIdx.x;

    for (int i = tid; i < 2400;  i += 1024) sm[SM_W2  + i] = w2[i];
    for (int i = tid; i < 10080; i += 1024) sm[SM_FW1 + i] = fw1[i];
    for (int i = tid; i < 840;   i += 1024) sm[SM_FW2 + i] = fw2[i];
    for (int i = tid; i < (SM_ZEND - SM_ZBEG); i += 1024) sm[SM_ZBEG + i] = 0.0f;
    if (tid == 0) {
        while (((volatile int*)g_ready)[b] == 0) __nanosleep(64);
    }
    __syncthreads();
    __threadfence();
    {
        const float4* src = (const float4*)(g_drive1 + (size_t)b * 4704);
        float4* dst = (float4*)(sm + SM_DRV);
        for (int i = tid; i < 1176; i += 1024) dst[i] = src[i];
    }
    __syncthreads();

    // ---- static mappings ----
    const int a_c  = tid / 98;                 // A: tid<588 (c, by, p)
    const int a_r  = tid % 98;
    const int a_by = a_r / 7;
    const int a_p  = a_r % 7;
    const int c2_oc  = tid / 30;               // B1: tid<480 (oc, ic, oy2)
    const int c2_rm  = tid % 30;
    const int c2_ic  = c2_rm / 5;
    const int c2_oy2 = c2_rm % 5;
    const int c_sp = tid >> 7;                 // C1: tid<512, o2<60
    const int c_o2 = tid & 127;
    const int d_g  = tid >> 3;                 // D: tid<672
    const int d_j  = tid & 7;

    // register-resident LIF state
    float pm1[2] = {0.f, 0.f}, pm2[2] = {0.f, 0.f};       // layer2 pooled
    float qm1 = 0.f, qm2 = 0.f;                            // layer4 pooled
    float em1a = 0.f, em2a = 0.f, em1b = 0.f, em2b = 0.f;  // layer5

#pragma unroll 1
    for (int t = 0; t < T_STEPS; t++) {
        // ---- A': lif1(drive from smem) + pool + lif2 -> SKB ----
        if (tid < 588) {
            const float* dp = sm + SM_DRV + (t & 1) * 4704
                            + a_c * 784 + (2 * a_by) * 28 + 4 * a_p;
            float4 v0 = *(const float4*)dp;
            float4 v1 = *(const float4*)(dp + 28);
            float acc[8] = {v0.x, v0.y, v0.z, v0.w, v1.x, v1.y, v1.z, v1.w};
            int ob = a_c * 784 + (2 * a_by) * 28 + 4 * a_p;
            float ps[2] = {0.f, 0.f};
#pragma unroll
            for (int q = 0; q < 8; q++) {
                int oy = q >> 2, j = q & 3;
                int o = ob + oy * 28 + j;
                float2 m = *(float2*)(sm + SM_M12A + 2 * o);
                float oms = (m.y > 0.3f) ? 0.f : 1.f;
                float n1 = m.x * 0.25f * oms + acc[q];
                float n2 = m.y * 0.25f * oms + 0.5f * n1;
                *(float2*)(sm + SM_M12A + 2 * o) = make_float2(n1, n2);
                ps[j >> 1] += (n2 > 0.3f) ? 1.f : 0.f;
            }
#pragma unroll
            for (int h = 0; h < 2; h++) {
                float d   = 0.25f * ps[h];
                float oms = (pm2[h] > 0.3f) ? 0.f : 1.f;
                float n1  = pm1[h] * 0.25f * oms + d;
                float n2  = pm2[h] * 0.25f * oms + 0.5f * n1;
                pm1[h] = n1; pm2[h] = n2;
                sm[SM_SKB + a_c * 196 + a_by * 14 + 2 * a_p + h] = (n2 > 0.3f) ? 1.f : 0.f;
            }
        }
        __syncthreads();

        // ---- B1: conv2 partials (20 outputs, rolling rows) | drive prefetch ----
        if (tid < 480) {
            const float* wr = sm + SM_W2 + (c2_oc * 6 + c2_ic) * 25;
            const float* ib = sm + SM_SKB + c2_ic * 196;
            float acc[20];
#pragma unroll
            for (int q = 0; q < 20; q++) acc[q] = 0.f;
#pragma unroll
            for (int r = 0; r < 6; r++) {
                const float2* rp = (const float2*)(ib + (2 * c2_oy2 + r) * 14);
                float in[14];
#pragma unroll
                for (int k = 0; k < 7; k++) {
                    float2 v = rp[k];
                    in[2 * k] = v.x; in[2 * k + 1] = v.y;
                }
                if (r < 5) {
#pragma unroll
                    for (int kx = 0; kx < 5; kx++) {
                        float wv = wr[r * 5 + kx];
#pragma unroll
                        for (int ox = 0; ox < 10; ox++)
                            acc[ox] = fmaf(wv, in[kx + ox], acc[ox]);
                    }
                }
                if (r >= 1) {
#pragma unroll
                    for (int kx = 0; kx < 5; kx++) {
                        float wv = wr[(r - 1) * 5 + kx];
#pragma unroll
                        for (int ox = 0; ox < 10; ox++)
                            acc[10 + ox] = fmaf(wv, in[kx + ox], acc[10 + ox]);
                    }
                }
            }
            float2* pp = (float2*)(sm + SM_PARTB + c2_ic * 1600 + c2_oc * 100 + (2 * c2_oy2) * 10);
#pragma unroll
            for (int q = 0; q < 10; q++)
                pp[q] = make_float2(acc[2 * q], acc[2 * q + 1]);
        } else if (t + 1 < T_STEPS) {
            int idx = (t + 1) * 32 + b;
            if (lane == 0) {
                while (((volatile int*)g_ready)[idx] == 0) __nanosleep(64);
            }
            __syncwarp();
            __threadfence();
            const float4* src = (const float4*)(g_drive1 + (size_t)idx * 4704);
            float4* dst = (float4*)(sm + SM_DRV + ((t + 1) & 1) * 4704);
            for (int i = tid - 480; i < 1176; i += 544) dst[i] = src[i];
        }
        __syncthreads();

        // ---- B2: reduce ic + lif3 + pool + lif4 + per-warp spike segments ----
        bool spiked = false;
        int myk = 0;
        if (tid < 400) {
            int oc = tid / 25, rem = tid % 25, py = rem / 5, px = rem % 5;
            float s00 = 0.f, s01 = 0.f, s10 = 0.f, s11 = 0.f;
#pragma unroll
            for (int ic = 0; ic < 6; ic++) {
                const float* pb = sm + SM_PARTB + ic * 1600 + oc * 100;
                float2 va = *(const float2*)(pb + (2 * py) * 10 + 2 * px);
                float2 vb = *(const float2*)(pb + (2 * py + 1) * 10 + 2 * px);
                s00 += va.x; s01 += va.y; s10 += vb.x; s11 += vb.y;
            }
            float dr0[4] = {s00, s01, s10, s11};
            float psum = 0.f;
            int ob = oc * 100 + (2 * py) * 10 + 2 * px;
#pragma unroll
            for (int q = 0; q < 4; q++) {
                int o = ob + (q >> 1) * 10 + (q & 1);
                float2 m = *(float2*)(sm + SM_M12C + 2 * o);
                float oms = (m.y > 0.3f) ? 0.f : 1.f;
                float n1 = m.x * 0.25f * oms + dr0[q];
                float n2 = m.y * 0.25f * oms + 0.5f * n1;
                *(float2*)(sm + SM_M12C + 2 * o) = make_float2(n1, n2);
                psum += (n2 > 0.3f) ? 1.f : 0.f;
            }
            float d   = 0.25f * psum;
            float oms = (qm2 > 0.3f) ? 0.f : 1.f;
            float n1  = qm1 * 0.25f * oms + d;
            float n2  = qm2 * 0.25f * oms + 0.5f * n1;
            qm1 = n1; qm2 = n2;
            if (n2 > 0.3f) { spiked = true; myk = tid; }
        }
        {
            unsigned bm = __ballot_sync(0xffffffffu, spiked);
            if (spiked) listi[wrp * 32 + __popc(bm & ((1u << lane) - 1u))] = myk;
            if (lane == 0 && wrp < 13) wcnt[wrp] = __popc(bm);
        }
        __syncthreads();

        // ---- C1: sparse conv3 gather (u64 pairs), 4-way segment split ----
        u64 cacc = 0ull;
        if (tid < 512 && c_o2 < 60) {
            const u64* w3p = (const u64*)g_w3t;
            for (int w = c_sp; w < 13; w += 4) {
                int n = wcnt[w];
                const int* seg = listi + w * 32;
                for (int j = 0; j < n; j++) {
                    int k = seg[j];
                    add2(cacc, __ldg(w3p + k * 60 + c_o2));
                }
            }
            if (c_sp) *(u64*)(sm + SM_PARTC + (c_sp - 1) * 120 + 2 * c_o2) = cacc;
        }
        __syncthreads();

        // ---- C2: combine + lif5 -> SKE ----
        if (tid < 60) {
            add2(cacc, *(const u64*)(sm + SM_PARTC + 2 * tid));
            add2(cacc, *(const u64*)(sm + SM_PARTC + 120 + 2 * tid));
            add2(cacc, *(const u64*)(sm + SM_PARTC + 240 + 2 * tid));
            float2 v = u2f(cacc);
            float oms = (em2a > 0.3f) ? 0.f : 1.f;
            float n1  = em1a * 0.25f * oms + v.x;
            float n2  = em2a * 0.25f * oms + 0.5f * n1;
            em1a = n1; em2a = n2;
            sm[SM_SKE + 2 * tid] = (n2 > 0.3f) ? 1.f : 0.f;
            float omsb = (em2b > 0.3f) ? 0.f : 1.f;
            float n1b  = em1b * 0.25f * omsb + v.y;
            float n2b  = em2b * 0.25f * omsb + 0.5f * n1b;
            em1b = n1b; em2b = n2b;
            sm[SM_SKE + 2 * tid + 1] = (n2b > 0.3f) ? 1.f : 0.f;
        }
        __syncthreads();

        // ---- D: fc1 + lif6 -> SKF ----
        if (tid < 672) {
            const float* wp = sm + SM_FW1 + d_g * 120;
            float s = 0.f;
#pragma unroll
            for (int k = d_j; k < 120; k += 8) s = fmaf(wp[k], sm[SM_SKE + k], s);
            s += __shfl_xor_sync(0xffffffffu, s, 4);
            s += __shfl_xor_sync(0xffffffffu, s, 2);
            s += __shfl_xor_sync(0xffffffffu, s, 1);
            if (d_j == 0) {
                float2 m = *(float2*)(sm + SM_M12F + 2 * d_g);
                float oms = (m.y > 0.3f) ? 0.f : 1.f;
                float n1 = m.x * 0.25f * oms + s;
                float n2 = m.y * 0.25f * oms + 0.5f * n1;
                *(float2*)(sm + SM_M12F + 2 * d_g) = make_float2(n1, n2);
                sm[SM_SKF + d_g] = (n2 > 0.3f) ? 1.f : 0.f;
            }
        }
        __syncthreads();

        // ---- E: fc2 + lif7 + acc (warps 0-9) ----
        if (wrp < 10) {
            const float* wp = sm + SM_FW2 + wrp * 84;
            float s = 0.f;
            for (int k = lane; k < 84; k += 32) s = fmaf(wp[k], sm[SM_SKF + k], s);
#pragma unroll
            for (int d2 = 16; d2 > 0; d2 >>= 1) s += __shfl_xor_sync(0xffffffffu, s, d2);
            if (lane == 0) {
                float2 m = *(float2*)(sm + SM_M12G + 2 * wrp);
                float oms = (m.y > 0.3f) ? 0.f : 1.f;
                float n1 = m.x * 0.25f * oms + s;
                float n2 = m.y * 0.25f * oms + 0.5f * n1;
                *(float2*)(sm + SM_M12G + 2 * wrp) = make_float2(n1, n2);
                sm[SM_ACC + wrp] += (n2 > 0.3f) ? 1.f : 0.f;
            }
        }
        __syncthreads();
    }

    if (tid < 10)
        out[b * 10 + tid] = sm[SM_ACC + tid] * (1.0f / 512.0f);
}

extern "C" void kernel_launch(void* const* d_in, const int* in_sizes, int n_in,
                              void* d_out, int out_size)
{
    const float* image = (const float*)d_in[0];
    const float* w1    = (const float*)d_in[1];
    const float* w2    = (const float*)d_in[2];
    const float* w3    = (const float*)d_in[3];
    const float* fw1   = (const float*)d_in[4];
    const float* fw2   = (const float*)d_in[5];
    float* out = (float*)d_out;

    reset_kernel<<<(N_TILES + 1023) / 1024, 1024>>>();
    w3t_kernel<<<(48000 + 255) / 256, 256>>>(w3);
    cudaFuncSetAttribute(fused_kernel, cudaFuncAttributeMaxDynamicSharedMemorySize, SMEM_BYTES);
    fused_kernel<<<N_SIM + N_PROD, 1024, SMEM_BYTES>>>(image, w1, w2, fw1, fw2, out);
}